// round 4
// baseline (speedup 1.0000x reference)
#include <cuda_runtime.h>
#include <cuda_bf16.h>
#include <math.h>

#define N_   131072
#define D_   64
#define K_   2048
#define RPB  128              // rows per block
#define CPB  256              // codes per chunk
#define NCH  (K_ / CPB)       // 8 chunks
#define XSS  132              // padded xs stride (floats)
#define TPB  256
#define GRID (N_ / RPB)       // 1024 blocks
#define MARG    0.009f
#define MARG_FX 299           // fixed-point refilter slack (0.009*32767 + quant slack)
#define QTH  88               // per-thread queue capacity

typedef unsigned int u32;
typedef unsigned long long u64;

// B row stride: 64 bf16 data padded to 72 halves = 144B (conflict-free LDS)
#define BPAD 72

// Device scratch (no allocations allowed)
__device__ __align__(16) float         g_en  [K_ * D_];    // normalized codebook fp32
__device__ __align__(16) float         g_see [K_];         // sum(en^2) per code
__device__ __align__(16) __nv_bfloat16 g_enbp[K_ * BPAD];  // bf16, 144B-padded rows
__device__ float g_part[GRID];

// ---- smem byte offsets ----
#define OFF_A    0            // 128*144 = 18432   A bf16 [row][72h]
#define OFF_B0   18432        // 36864             B buf0 [code][72h]
#define OFF_B1   55296        // 36864             B buf1
#define OFF_XS   92160        // 33792             xs fp32 [64][132]
#define OFF_SXX  125952       // 512
#define OFF_RMX  126464       // 512               u32[128] fixed-point row max
#define OFF_RB   126976       // 1024              u64[128] packed (valbits, code)
#define OFF_Q    128000       // 256*88*4 = 90112  private queues
#define DYNSMEM  218112

// ---------------- helpers ----------------
__device__ __forceinline__ u32 smem_u32(const void* p) {
    u32 a; asm("{ .reg .u64 t; cvta.to.shared.u64 t, %1; cvt.u32.u64 %0, t; }" : "=r"(a) : "l"(p));
    return a;
}
__device__ __forceinline__ void cp16(u32 dst, const void* src) {
    asm volatile("cp.async.cg.shared.global [%0], [%1], 16;" :: "r"(dst), "l"(src) : "memory");
}
__device__ __forceinline__ void cp_commit() { asm volatile("cp.async.commit_group;" ::: "memory"); }
template<int W> __device__ __forceinline__ void cp_wait() {
    asm volatile("cp.async.wait_group %0;" :: "n"(W) : "memory");
}
__device__ __forceinline__ void mma16816(float* c, const u32* a, u32 b0, u32 b1) {
    asm volatile("mma.sync.aligned.m16n8k16.row.col.f32.bf16.bf16.f32 "
        "{%0,%1,%2,%3}, {%4,%5,%6,%7}, {%8,%9}, {%0,%1,%2,%3};"
        : "+f"(c[0]), "+f"(c[1]), "+f"(c[2]), "+f"(c[3])
        : "r"(a[0]), "r"(a[1]), "r"(a[2]), "r"(a[3]), "r"(b0), "r"(b1));
}
__device__ __forceinline__ u32 fix16(float v) {
    float c = fminf(fmaxf(fmaf(v, 32767.f, 32768.f), 0.f), 65535.f);
    return (u32)c;
}
// exact fp32 rescore (same formula/order as round-2 passing kernel) + atomicMin key
__device__ __noinline__ void exact_rescore(const float* xs, const float* sxx,
                                           u64* rbest, int row, int code) {
    float dot = 0.f;
    const float* er = g_en + code * 64;
    #pragma unroll
    for (int d = 0; d < 64; d++) dot = fmaf(xs[d * XSS + row], er[d], dot);
    float val = fmaf(-2.0f, dot, sxx[row] + g_see[code]);
    u32 vb = __float_as_uint(val);
    vb = (vb & 0x80000000u) ? ~vb : (vb | 0x80000000u);     // order-preserving
    u64 key = ((u64)vb << 32) | (u32)code;
    atomicMin(rbest + row, key);                            // min val, tie -> min idx
}

// ---------------------------------------------------------------------------
// Kernel 1: normalize embeddings -> g_en (fp32), g_see, g_enbp (bf16 padded).
// ---------------------------------------------------------------------------
__global__ void vq_norm_emb(const float* __restrict__ emb) {
    int w    = (blockIdx.x * blockDim.x + threadIdx.x) >> 5;
    int lane = threadIdx.x & 31;
    if (w >= K_) return;
    float v0 = emb[w * 64 + lane];
    float v1 = emb[w * 64 + lane + 32];
    float s  = v0 * v0 + v1 * v1;
    #pragma unroll
    for (int o = 16; o > 0; o >>= 1) s += __shfl_xor_sync(0xffffffffu, s, o);
    float inv = 1.0f / fmaxf(sqrtf(s), 1e-12f);
    float e0 = v0 * inv, e1 = v1 * inv;
    g_en[w * 64 + lane]      = e0;
    g_en[w * 64 + lane + 32] = e1;
    float t = e0 * e0 + e1 * e1;   // see from ROUNDED values (matches reference)
    #pragma unroll
    for (int o = 16; o > 0; o >>= 1) t += __shfl_xor_sync(0xffffffffu, t, o);
    if (lane == 0) g_see[w] = t;
    g_enbp[w * BPAD + lane]      = __float2bfloat16(e0);
    g_enbp[w * BPAD + lane + 32] = __float2bfloat16(e1);
}

// ---------------------------------------------------------------------------
// Kernel 2: HMMA bf16 screening GEMM + private-queue margin + exact rescore.
// ---------------------------------------------------------------------------
extern __shared__ char smem_[];

__global__ void __launch_bounds__(TPB, 1)
vq_main(const float* __restrict__ x, float* __restrict__ out, int out_size) {
    char* base = smem_;
    float* xs    = (float*)(base + OFF_XS);
    float* sxx   = (float*)(base + OFF_SXX);
    u32*   rmaxs = (u32*)  (base + OFF_RMX);
    u64*   rbest = (u64*)  (base + OFF_RB);
    u32*   myq   = (u32*)  (base + OFF_Q) + threadIdx.x * QTH;

    int tid  = threadIdx.x;
    int warp = tid >> 5, lane = tid & 31;
    int g  = lane >> 2;            // groupID
    int tq = lane & 3;             // thread-in-group
    int wy = warp & 3;             // row block (32 rows)
    int wx = warp >> 2;            // col half (128 codes per chunk)
    int rowbase = blockIdx.x * RPB;

    if (tid < RPB) { rbest[tid] = 0xFFFFFFFFFFFFFFFFull; rmaxs[tid] = 0u; }

    // prefetch B chunk 0 (32KB data into 144B-padded rows)
    {
        u32 dst = smem_u32(base + OFF_B0) + (u32)tid * 144u;
        const __nv_bfloat16* src = g_enbp + (size_t)tid * BPAD;
        #pragma unroll
        for (int i = 0; i < 8; i++) cp16(dst + i * 16u, src + i * 8);
        cp_commit();
    }

    // load x tile, transposed
    #pragma unroll
    for (int i = 0; i < 32; i++) {
        int e = i * TPB + tid;
        int r = e >> 6, d = e & 63;
        xs[d * XSS + r] = x[(rowbase + r) * 64 + d];
    }
    __syncthreads();

    // normalize rows; sxx
    if (tid < RPB) {
        float s = 0.f;
        #pragma unroll
        for (int d = 0; d < 64; d++) { float v = xs[d * XSS + tid]; s += v * v; }
        float inv = 1.0f / fmaxf(sqrtf(s), 1e-12f);
        float s2 = 0.f;
        #pragma unroll
        for (int d = 0; d < 64; d++) {
            float v = xs[d * XSS + tid] * inv;
            xs[d * XSS + tid] = v;
            s2 += v * v;
        }
        sxx[tid] = s2;
    }
    __syncthreads();

    // A tile bf16 [row][72 halves]
    #pragma unroll
    for (int i = 0; i < 32; i++) {
        int e = i * TPB + tid;
        int r = e >> 6, d = e & 63;
        *(__nv_bfloat16*)(base + OFF_A + r * 144 + d * 2) =
            __float2bfloat16(xs[d * XSS + r]);
    }
    __syncthreads();

    // A fragments: persist in registers for all chunks
    u32 af[2][4][4];
    #pragma unroll
    for (int mt = 0; mt < 2; mt++) {
        int r0 = wy * 32 + mt * 16 + g;
        #pragma unroll
        for (int k = 0; k < 4; k++) {
            int c0 = (k * 16 + tq * 2) * 2;
            af[mt][k][0] = *(const u32*)(base + OFF_A + r0 * 144 + c0);
            af[mt][k][1] = *(const u32*)(base + OFF_A + (r0 + 8) * 144 + c0);
            af[mt][k][2] = *(const u32*)(base + OFF_A + r0 * 144 + c0 + 16);
            af[mt][k][3] = *(const u32*)(base + OFF_A + (r0 + 8) * 144 + c0 + 16);
        }
    }

    float rm00 = -1e30f, rm01 = -1e30f, rm10 = -1e30f, rm11 = -1e30f;
    int qn = 0;

    for (int ch = 0; ch < NCH; ch++) {
        if (ch + 1 < NCH) {
            u32 dst = smem_u32(base + (((ch + 1) & 1) ? OFF_B1 : OFF_B0)) + (u32)tid * 144u;
            const __nv_bfloat16* src = g_enbp + (size_t)((ch + 1) * CPB + tid) * BPAD;
            #pragma unroll
            for (int i = 0; i < 8; i++) cp16(dst + i * 16u, src + i * 8);
            cp_commit();
            cp_wait<1>();     // chunk ch landed
        } else {
            cp_wait<0>();
        }
        __syncthreads();

        const char* Bs = base + ((ch & 1) ? OFF_B1 : OFF_B0);

        #pragma unroll
        for (int ng = 0; ng < 2; ng++) {
            float acc[2][8][4];
            #pragma unroll
            for (int mt = 0; mt < 2; mt++)
                #pragma unroll
                for (int nt = 0; nt < 8; nt++)
                    #pragma unroll
                    for (int q = 0; q < 4; q++) acc[mt][nt][q] = 0.f;

            #pragma unroll
            for (int k = 0; k < 4; k++) {
                #pragma unroll
                for (int nt = 0; nt < 8; nt++) {
                    int cr = wx * 128 + ng * 64 + nt * 8 + g;
                    int co = (k * 16 + tq * 2) * 2;
                    u32 b0 = *(const u32*)(Bs + cr * 144 + co);
                    u32 b1 = *(const u32*)(Bs + cr * 144 + co + 16);
                    mma16816(acc[0][nt], af[0][k], b0, b1);
                    mma16816(acc[1][nt], af[1][k], b0, b1);
                }
            }

            // pass 1: update running maxima over the whole 64-code group
            #pragma unroll
            for (int nt = 0; nt < 8; nt++) {
                rm00 = fmaxf(rm00, fmaxf(acc[0][nt][0], acc[0][nt][1]));
                rm01 = fmaxf(rm01, fmaxf(acc[0][nt][2], acc[0][nt][3]));
                rm10 = fmaxf(rm10, fmaxf(acc[1][nt][0], acc[1][nt][1]));
                rm11 = fmaxf(rm11, fmaxf(acc[1][nt][2], acc[1][nt][3]));
            }
            // pass 2: push candidates within margin of updated maxima
            float t00 = rm00 - MARG, t01 = rm01 - MARG;
            float t10 = rm10 - MARG, t11 = rm11 - MARG;
            #pragma unroll
            for (int nt = 0; nt < 8; nt++) {
                int c0 = ch * CPB + wx * 128 + ng * 64 + nt * 8 + tq * 2;
                #pragma unroll
                for (int mt = 0; mt < 2; mt++) {
                    float th0 = mt ? t10 : t00;
                    float th1 = mt ? t11 : t01;
                    #pragma unroll
                    for (int q = 0; q < 4; q++) {
                        float v = acc[mt][nt][q];
                        float th = (q < 2) ? th0 : th1;
                        if (v > th) {
                            int sid  = mt * 2 + (q >> 1);
                            int code = c0 + (q & 1);
                            if (qn >= QTH) {          // purge stale entries (cold)
                                int w2 = 0;
                                for (int i = 0; i < qn; i++) {
                                    u32 e = myq[i];
                                    int s = (e >> 11) & 3;
                                    float rv = (s == 0) ? rm00 : (s == 1) ? rm01
                                             : (s == 2) ? rm10 : rm11;
                                    if ((e >> 16) + 4 >= fix16(rv - MARG)) myq[w2++] = e;
                                }
                                qn = w2;
                            }
                            if (qn < QTH)
                                myq[qn++] = (fix16(v) << 16) | ((u32)sid << 11) | (u32)code;
                            else    // still full: guaranteed-correct fallback
                                exact_rescore(xs, sxx, rbest,
                                    wy * 32 + mt * 16 + g + (q >> 1) * 8, code);
                        }
                    }
                }
            }
        }
        __syncthreads();
    }

    // true per-row max (fixed-point) across all threads
    atomicMax(&rmaxs[wy * 32 + g],           fix16(rm00));
    atomicMax(&rmaxs[wy * 32 + g + 8],       fix16(rm01));
    atomicMax(&rmaxs[wy * 32 + 16 + g],      fix16(rm10));
    atomicMax(&rmaxs[wy * 32 + 16 + g + 8],  fix16(rm11));
    __syncthreads();

    // refilter private queue against true row max; exact-rescore survivors
    for (int i = 0; i < qn; i++) {
        u32 e = myq[i];
        int code = e & 2047;
        int s    = (e >> 11) & 3;
        int row  = wy * 32 + (s >> 1) * 16 + g + (s & 1) * 8;
        u32 fx   = e >> 16;
        if (fx + MARG_FX >= rmaxs[row])
            exact_rescore(xs, sxx, rbest, row, code);
    }
    __syncthreads();

    // ---- per-row final: quantized_st, idx, loss ----
    float lsum = 0.f;
    if (tid < RPB) {
        int bk = (int)(rbest[tid] & 2047u);
        float inv2 = 1.0f / fmaxf(sqrtf(g_see[bk]), 1e-12f);
        const float* erow = g_en + bk * 64;
        #pragma unroll
        for (int d = 0; d < 64; d++) {
            float xnv  = xs[d * XSS + tid];
            float qd   = erow[d] * inv2;
            float diff = qd - xnv;
            lsum += diff * diff;
            xs[d * XSS + tid] = xnv + diff;
        }
        if (out_size >= N_ * D_ + 1 + N_)
            out[N_ * D_ + 1 + rowbase + tid] = (float)bk;
    }
    __syncthreads();

    // coalesced store of quantized_st
    #pragma unroll
    for (int i = 0; i < 32; i++) {
        int e = i * TPB + tid;
        out[rowbase * 64 + e] = xs[(e & 63) * XSS + (e >> 6)];
    }

    // deterministic block loss reduction (reuse sxx region + rmaxs as float)
    float* red = (float*)(base + OFF_RMX);
    if (tid < RPB) red[tid] = lsum;
    __syncthreads();
    for (int s = 64; s > 0; s >>= 1) {
        if (tid < s) red[tid] += red[tid + s];
        __syncthreads();
    }
    if (tid == 0) g_part[blockIdx.x] = red[0];
}

// ---------------------------------------------------------------------------
// Kernel 3: deterministic final loss reduction.
// loss = q_latent + 0.25*e_latent = 1.25 * mean((q - xn)^2)
// ---------------------------------------------------------------------------
__global__ void vq_final(float* __restrict__ out, int out_size) {
    __shared__ float sm[256];
    int tid = threadIdx.x;
    float s = g_part[tid] + g_part[tid + 256] + g_part[tid + 512] + g_part[tid + 768];
    sm[tid] = s;
    __syncthreads();
    for (int st = 128; st > 0; st >>= 1) {
        if (tid < st) sm[tid] += sm[tid + st];
        __syncthreads();
    }
    if (tid == 0 && out_size > N_ * D_)
        out[N_ * D_] = 1.25f * (sm[0] / (float)(N_ * D_));
}

// ---------------------------------------------------------------------------
extern "C" void kernel_launch(void* const* d_in, const int* in_sizes, int n_in,
                              void* d_out, int out_size) {
    const float* x;
    const float* emb;
    if (n_in >= 2 && in_sizes[0] >= in_sizes[1]) {
        x = (const float*)d_in[0]; emb = (const float*)d_in[1];
    } else {
        x = (const float*)d_in[1]; emb = (const float*)d_in[0];
    }

    cudaFuncSetAttribute(vq_main, cudaFuncAttributeMaxDynamicSharedMemorySize, DYNSMEM);

    vq_norm_emb<<<K_ / 8, 256>>>(emb);
    vq_main<<<GRID, TPB, DYNSMEM>>>(x, (float*)d_out, out_size);
    vq_final<<<1, 256>>>((float*)d_out, out_size);
}

// round 5
// speedup vs baseline: 1.6844x; 1.6844x over previous
#include <cuda_runtime.h>
#include <cuda_bf16.h>
#include <math.h>

#define N_   131072
#define D_   64
#define K_   2048
#define RPB  128              // rows per block
#define CPB  256              // codes per chunk
#define NCH  (K_ / CPB)       // 8 chunks
#define XSS  132              // padded xs stride (floats)
#define TPB  512
#define GRID (N_ / RPB)       // 1024 blocks
#define MARG    0.009f        // > 2x bf16 unit-dot error bound (validated R4)
#define MARG_FX 299
#define QTH  32               // per-thread queue capacity

typedef unsigned int u32;
typedef unsigned long long u64;

#define BPAD 72               // bf16 row pad: 144B rows, conflict-free LDS

// Device scratch (no allocations allowed)
__device__ __align__(16) float         g_en  [K_ * D_];
__device__ __align__(16) float         g_see [K_];
__device__ __align__(16) __nv_bfloat16 g_enbp[K_ * BPAD];
__device__ float g_part[GRID];

// ---- smem byte offsets ----
#define OFF_A    0            // 18432  A bf16 [128][72h]
#define OFF_B0   18432        // 36864  B buf0 [256][72h]
#define OFF_B1   55296        // 36864  B buf1
#define OFF_XS   92160        // 33792  xs fp32 [64][132]
#define OFF_SXX  125952       // 512
#define OFF_RB   126464       // 1024   u64[128] packed (valbits, code)
#define OFF_Q    127488       // 65536  queues, interleaved [i][tid]
#define DYNSMEM  193024

// ---------------- helpers ----------------
__device__ __forceinline__ u32 smem_u32(const void* p) {
    u32 a; asm("{ .reg .u64 t; cvta.to.shared.u64 t, %1; cvt.u32.u64 %0, t; }" : "=r"(a) : "l"(p));
    return a;
}
__device__ __forceinline__ void cp16(u32 dst, const void* src) {
    asm volatile("cp.async.cg.shared.global [%0], [%1], 16;" :: "r"(dst), "l"(src) : "memory");
}
__device__ __forceinline__ void cp_commit() { asm volatile("cp.async.commit_group;" ::: "memory"); }
template<int W> __device__ __forceinline__ void cp_wait() {
    asm volatile("cp.async.wait_group %0;" :: "n"(W) : "memory");
}
__device__ __forceinline__ void mma16816(float* c, const u32* a, u32 b0, u32 b1) {
    asm volatile("mma.sync.aligned.m16n8k16.row.col.f32.bf16.bf16.f32 "
        "{%0,%1,%2,%3}, {%4,%5,%6,%7}, {%8,%9}, {%0,%1,%2,%3};"
        : "+f"(c[0]), "+f"(c[1]), "+f"(c[2]), "+f"(c[3])
        : "r"(a[0]), "r"(a[1]), "r"(a[2]), "r"(a[3]), "r"(b0), "r"(b1));
}
__device__ __forceinline__ u32 fix16(float v) {
    float c = fminf(fmaxf(fmaf(v, 32767.f, 32768.f), 0.f), 65535.f);
    return (u32)c;
}
// exact fp32 rescore (identical formula/order to passing R2/R4) + atomicMin key
__device__ __noinline__ void exact_rescore(const float* xs, const float* sxx,
                                           u64* rbest, int row, int code) {
    float dot = 0.f;
    const float* er = g_en + code * 64;
    #pragma unroll
    for (int d = 0; d < 64; d++) dot = fmaf(xs[d * XSS + row], er[d], dot);
    float val = fmaf(-2.0f, dot, sxx[row] + g_see[code]);
    u32 vb = __float_as_uint(val);
    vb = (vb & 0x80000000u) ? ~vb : (vb | 0x80000000u);
    u64 key = ((u64)vb << 32) | (u32)code;
    atomicMin(rbest + row, key);
}

// ---------------------------------------------------------------------------
// Kernel 1: normalize embeddings -> g_en (fp32), g_see, g_enbp (bf16 padded).
// ---------------------------------------------------------------------------
__global__ void vq_norm_emb(const float* __restrict__ emb) {
    int w    = (blockIdx.x * blockDim.x + threadIdx.x) >> 5;
    int lane = threadIdx.x & 31;
    if (w >= K_) return;
    float v0 = emb[w * 64 + lane];
    float v1 = emb[w * 64 + lane + 32];
    float s  = v0 * v0 + v1 * v1;
    #pragma unroll
    for (int o = 16; o > 0; o >>= 1) s += __shfl_xor_sync(0xffffffffu, s, o);
    float inv = 1.0f / fmaxf(sqrtf(s), 1e-12f);
    float e0 = v0 * inv, e1 = v1 * inv;
    g_en[w * 64 + lane]      = e0;
    g_en[w * 64 + lane + 32] = e1;
    float t = e0 * e0 + e1 * e1;   // see from ROUNDED values (matches reference)
    #pragma unroll
    for (int o = 16; o > 0; o >>= 1) t += __shfl_xor_sync(0xffffffffu, t, o);
    if (lane == 0) g_see[w] = t;
    g_enbp[w * BPAD + lane]      = __float2bfloat16(e0);
    g_enbp[w * BPAD + lane + 32] = __float2bfloat16(e1);
}

// ---------------------------------------------------------------------------
// Kernel 2: HMMA bf16 screening GEMM + group-max margin queue + exact rescore.
// 512 threads: 16 warps as 4(wy) x 4(wx); warp tile 32 rows x 64 codes/chunk.
// ---------------------------------------------------------------------------
extern __shared__ char smem_[];

__global__ void __launch_bounds__(TPB, 1)
vq_main(const float* __restrict__ x, float* __restrict__ out, int out_size) {
    char* base = smem_;
    float* xs   = (float*)(base + OFF_XS);
    float* sxx  = (float*)(base + OFF_SXX);
    u64*   rbest= (u64*)  (base + OFF_RB);
    u32*   qbuf = (u32*)  (base + OFF_Q);     // entry i of thread t at [i*TPB + t]

    int tid  = threadIdx.x;
    int warp = tid >> 5, lane = tid & 31;
    int g  = lane >> 2;            // groupID (0..7)
    int tq = lane & 3;             // thread-in-group
    int wy = warp & 3;             // row block (32 rows)
    int wx = warp >> 2;            // col quarter (64 codes per chunk)
    int rowbase = blockIdx.x * RPB;

    if (tid < RPB) rbest[tid] = 0xFFFFFFFFFFFFFFFFull;

    // prefetch B chunk 0: 512 threads, each 64B of a 144B row
    {
        int r = tid >> 1, h = tid & 1;
        u32 dst = smem_u32(base + OFF_B0) + (u32)r * 144u + (u32)h * 64u;
        const __nv_bfloat16* src = g_enbp + (size_t)r * BPAD + h * 32;
        #pragma unroll
        for (int i = 0; i < 4; i++) cp16(dst + i * 16u, src + i * 8);
        cp_commit();
    }

    // load x tile, transposed
    #pragma unroll
    for (int i = 0; i < 16; i++) {
        int e = i * TPB + tid;
        int r = e >> 6, d = e & 63;
        xs[d * XSS + r] = x[(rowbase + r) * 64 + d];
    }
    __syncthreads();

    // normalize rows; sxx
    if (tid < RPB) {
        float s = 0.f;
        #pragma unroll
        for (int d = 0; d < 64; d++) { float v = xs[d * XSS + tid]; s += v * v; }
        float inv = 1.0f / fmaxf(sqrtf(s), 1e-12f);
        float s2 = 0.f;
        #pragma unroll
        for (int d = 0; d < 64; d++) {
            float v = xs[d * XSS + tid] * inv;
            xs[d * XSS + tid] = v;
            s2 += v * v;
        }
        sxx[tid] = s2;
    }
    __syncthreads();

    // A tile bf16 [row][72 halves]
    #pragma unroll
    for (int i = 0; i < 16; i++) {
        int e = i * TPB + tid;
        int r = e >> 6, d = e & 63;
        *(__nv_bfloat16*)(base + OFF_A + r * 144 + d * 2) =
            __float2bfloat16(xs[d * XSS + r]);
    }
    __syncthreads();

    // A fragments (persist across all chunks): mapping validated in R4
    u32 af[2][4][4];
    #pragma unroll
    for (int mt = 0; mt < 2; mt++) {
        int r0 = wy * 32 + mt * 16 + g;
        #pragma unroll
        for (int k = 0; k < 4; k++) {
            int c0 = (k * 16 + tq * 2) * 2;
            af[mt][k][0] = *(const u32*)(base + OFF_A + r0 * 144 + c0);
            af[mt][k][1] = *(const u32*)(base + OFF_A + (r0 + 8) * 144 + c0);
            af[mt][k][2] = *(const u32*)(base + OFF_A + r0 * 144 + c0 + 16);
            af[mt][k][3] = *(const u32*)(base + OFF_A + (r0 + 8) * 144 + c0 + 16);
        }
    }

    float rm00 = -1e30f, rm01 = -1e30f, rm10 = -1e30f, rm11 = -1e30f;
    int qn = 0;

    // push with purge-on-full + guaranteed-correct inline fallback (R4 logic)
    auto push = [&](float v, int sid, int code) {
        if (qn >= QTH) {
            int w2 = 0;
            for (int i = 0; i < qn; i++) {
                u32 e = qbuf[i * TPB + tid];
                int s = (e >> 11) & 3;
                float rv = (s == 0) ? rm00 : (s == 1) ? rm01 : (s == 2) ? rm10 : rm11;
                if ((e >> 16) + 4 >= fix16(rv - MARG)) qbuf[w2++ * TPB + tid] = e;
            }
            qn = w2;
        }
        if (qn < QTH) {
            qbuf[qn * TPB + tid] = (fix16(v) << 16) | ((u32)sid << 11) | (u32)code;
            qn++;
        } else {
            exact_rescore(xs, sxx, rbest,
                wy * 32 + (sid >> 1) * 16 + (sid & 1) * 8 + g, code);
        }
    };

    for (int ch = 0; ch < NCH; ch++) {
        if (ch + 1 < NCH) {
            int r = tid >> 1, h = tid & 1;
            u32 dst = smem_u32(base + (((ch + 1) & 1) ? OFF_B1 : OFF_B0))
                      + (u32)r * 144u + (u32)h * 64u;
            const __nv_bfloat16* src = g_enbp + (size_t)((ch + 1) * CPB + r) * BPAD + h * 32;
            #pragma unroll
            for (int i = 0; i < 4; i++) cp16(dst + i * 16u, src + i * 8);
            cp_commit();
            cp_wait<1>();     // chunk ch landed
        } else {
            cp_wait<0>();
        }
        __syncthreads();

        const char* Bs = base + ((ch & 1) ? OFF_B1 : OFF_B0);

        #pragma unroll
        for (int ng = 0; ng < 2; ng++) {
            float acc[2][4][4];
            #pragma unroll
            for (int mt = 0; mt < 2; mt++)
                #pragma unroll
                for (int nt = 0; nt < 4; nt++)
                    #pragma unroll
                    for (int q = 0; q < 4; q++) acc[mt][nt][q] = 0.f;

            #pragma unroll
            for (int k = 0; k < 4; k++) {
                #pragma unroll
                for (int nt = 0; nt < 4; nt++) {
                    int cr = wx * 64 + ng * 32 + nt * 8 + g;
                    int co = k * 32 + tq * 4;
                    u32 b0 = *(const u32*)(Bs + cr * 144 + co);
                    u32 b1 = *(const u32*)(Bs + cr * 144 + co + 16);
                    mma16816(acc[0][nt], af[0][k], b0, b1);
                    mma16816(acc[1][nt], af[1][k], b0, b1);
                }
            }

            int cbase = ch * CPB + wx * 64 + ng * 32 + tq * 2;

            // group-max fast path per stream (8 values each)
            #pragma unroll
            for (int sid = 0; sid < 4; sid++) {
                int mt = sid >> 1, qh = (sid & 1) * 2;
                float gm = fmaxf(fmaxf(acc[mt][0][qh], acc[mt][0][qh + 1]),
                                 fmaxf(acc[mt][1][qh], acc[mt][1][qh + 1]));
                gm = fmaxf(gm, fmaxf(fmaxf(acc[mt][2][qh], acc[mt][2][qh + 1]),
                                     fmaxf(acc[mt][3][qh], acc[mt][3][qh + 1])));
                float rm = (sid == 0) ? rm00 : (sid == 1) ? rm01
                         : (sid == 2) ? rm10 : rm11;
                if (gm > rm - MARG) {                   // rare slow path
                    float th = fmaxf(rm, gm) - MARG;
                    #pragma unroll
                    for (int nt = 0; nt < 4; nt++) {
                        float v0 = acc[mt][nt][qh], v1 = acc[mt][nt][qh + 1];
                        if (v0 > th) push(v0, sid, cbase + nt * 8);
                        if (v1 > th) push(v1, sid, cbase + nt * 8 + 1);
                    }
                }
                rm = fmaxf(rm, gm);
                if (sid == 0) rm00 = rm; else if (sid == 1) rm01 = rm;
                else if (sid == 2) rm10 = rm; else rm11 = rm;
            }
        }
        __syncthreads();
    }

    // refilter queue vs final per-thread stream max (looser than row max: safe)
    for (int i = 0; i < qn; i++) {
        u32 e = qbuf[i * TPB + tid];
        int code = e & 2047;
        int sid  = (e >> 11) & 3;
        float rv = (sid == 0) ? rm00 : (sid == 1) ? rm01
                 : (sid == 2) ? rm10 : rm11;
        if ((e >> 16) + MARG_FX >= fix16(rv))
            exact_rescore(xs, sxx, rbest,
                wy * 32 + (sid >> 1) * 16 + (sid & 1) * 8 + g, code);
    }
    __syncthreads();

    // ---- per-row final: quantized_st, idx, loss ----
    float lsum = 0.f;
    if (tid < RPB) {
        int bk = (int)(rbest[tid] & 2047u);
        float inv2 = 1.0f / fmaxf(sqrtf(g_see[bk]), 1e-12f);
        const float* erow = g_en + bk * 64;
        #pragma unroll
        for (int d = 0; d < 64; d++) {
            float xnv  = xs[d * XSS + tid];
            float qd   = erow[d] * inv2;
            float diff = qd - xnv;
            lsum += diff * diff;
            xs[d * XSS + tid] = xnv + diff;
        }
        if (out_size >= N_ * D_ + 1 + N_)
            out[N_ * D_ + 1 + rowbase + tid] = (float)bk;
    }
    __syncthreads();

    // coalesced store of quantized_st
    #pragma unroll
    for (int i = 0; i < 16; i++) {
        int e = i * TPB + tid;
        out[rowbase * 64 + e] = xs[(e & 63) * XSS + (e >> 6)];
    }

    // deterministic block loss reduction
    float* red = (float*)(base + OFF_SXX);   // sxx no longer needed
    if (tid < RPB) red[tid] = lsum;
    __syncthreads();
    for (int s = 64; s > 0; s >>= 1) {
        if (tid < s) red[tid] += red[tid + s];
        __syncthreads();
    }
    if (tid == 0) g_part[blockIdx.x] = red[0];
}

// ---------------------------------------------------------------------------
// Kernel 3: deterministic final loss reduction.
// loss = q_latent + 0.25*e_latent = 1.25 * mean((q - xn)^2)
// ---------------------------------------------------------------------------
__global__ void vq_final(float* __restrict__ out, int out_size) {
    __shared__ float sm[256];
    int tid = threadIdx.x;
    float s = g_part[tid] + g_part[tid + 256] + g_part[tid + 512] + g_part[tid + 768];
    sm[tid] = s;
    __syncthreads();
    for (int st = 128; st > 0; st >>= 1) {
        if (tid < st) sm[tid] += sm[tid + st];
        __syncthreads();
    }
    if (tid == 0 && out_size > N_ * D_)
        out[N_ * D_] = 1.25f * (sm[0] / (float)(N_ * D_));
}

// ---------------------------------------------------------------------------
extern "C" void kernel_launch(void* const* d_in, const int* in_sizes, int n_in,
                              void* d_out, int out_size) {
    const float* x;
    const float* emb;
    if (n_in >= 2 && in_sizes[0] >= in_sizes[1]) {
        x = (const float*)d_in[0]; emb = (const float*)d_in[1];
    } else {
        x = (const float*)d_in[1]; emb = (const float*)d_in[0];
    }

    cudaFuncSetAttribute(vq_main, cudaFuncAttributeMaxDynamicSharedMemorySize, DYNSMEM);

    vq_norm_emb<<<K_ / 8, 256>>>(emb);
    vq_main<<<GRID, TPB, DYNSMEM>>>(x, (float*)d_out, out_size);
    vq_final<<<1, 256>>>((float*)d_out, out_size);
}